// round 1
// baseline (speedup 1.0000x reference)
#include <cuda_runtime.h>
#include <math.h>

#define Bb 4
#define Nn 128
#define Ll 20
#define Dd 512
#define SCALE 0.044194173824159216f  // 1/sqrt(512)

// ---------------- scratch (no allocations allowed) ----------------
__device__ float g_q  [Bb*Nn*Dd];   // 512x512
__device__ float g_k  [Bb*Ll*Dd];   // 80x512
__device__ float g_fbq[Bb*Nn*Dd];   // 512x512
__device__ float g_S  [Bb*Nn*Nn];   // 4x128x128 (softmaxed in place -> A_b)

// ---------------- generic NT GEMM: C[M,N] = A[M,K] * B[N,K]^T (+bias) ----
// BM=32, BN=64, BK=32, 256 threads, thread tile 2x4.
#define BM 32
#define BN 64
#define BK 32

__global__ void gemm_nt(const float* __restrict__ A, const float* __restrict__ Bmat,
                        const float* __restrict__ bias, float* __restrict__ C,
                        int M, int Ncols, int K,
                        int sA, int sB, int sC)
{
    int bz = blockIdx.z;
    A    += (long)bz * sA;
    Bmat += (long)bz * sB;
    C    += (long)bz * sC;

    int bm = blockIdx.y * BM;
    int bn = blockIdx.x * BN;

    __shared__ float Ast[BK][BM + 2];  // transposed: Ast[k][m]
    __shared__ float Bst[BK][BN + 4];  // transposed: Bst[k][n]

    int tid = threadIdx.x;            // 256
    int tr  = tid >> 4;               // 0..15 -> 2 rows each
    int tc  = tid & 15;               // 0..15 -> 4 cols each

    float acc[2][4];
#pragma unroll
    for (int i = 0; i < 2; i++)
#pragma unroll
        for (int j = 0; j < 4; j++) acc[i][j] = 0.f;

    int arow = tid >> 3;              // 0..31
    int acol = (tid & 7) * 4;         // 0..28
    int brow0 = tid >> 3;             // 0..31
    int brow1 = brow0 + 32;

    for (int k0 = 0; k0 < K; k0 += BK) {
        // load A tile (32 x 32): one float4 per thread
        float4 av = make_float4(0.f, 0.f, 0.f, 0.f);
        int gm = bm + arow;
        if (gm < M) av = *(const float4*)(A + (long)gm * K + k0 + acol);
        Ast[acol + 0][arow] = av.x;
        Ast[acol + 1][arow] = av.y;
        Ast[acol + 2][arow] = av.z;
        Ast[acol + 3][arow] = av.w;
        // load B tile (64 x 32): two float4 per thread
        float4 bv0 = make_float4(0.f, 0.f, 0.f, 0.f);
        float4 bv1 = make_float4(0.f, 0.f, 0.f, 0.f);
        int gn0 = bn + brow0, gn1 = bn + brow1;
        if (gn0 < Ncols) bv0 = *(const float4*)(Bmat + (long)gn0 * K + k0 + acol);
        if (gn1 < Ncols) bv1 = *(const float4*)(Bmat + (long)gn1 * K + k0 + acol);
        Bst[acol + 0][brow0] = bv0.x;
        Bst[acol + 1][brow0] = bv0.y;
        Bst[acol + 2][brow0] = bv0.z;
        Bst[acol + 3][brow0] = bv0.w;
        Bst[acol + 0][brow1] = bv1.x;
        Bst[acol + 1][brow1] = bv1.y;
        Bst[acol + 2][brow1] = bv1.z;
        Bst[acol + 3][brow1] = bv1.w;
        __syncthreads();

#pragma unroll
        for (int k = 0; k < BK; k++) {
            float2 a = *(const float2*)&Ast[k][tr * 2];
            float4 b = *(const float4*)&Bst[k][tc * 4];
            acc[0][0] = fmaf(a.x, b.x, acc[0][0]);
            acc[0][1] = fmaf(a.x, b.y, acc[0][1]);
            acc[0][2] = fmaf(a.x, b.z, acc[0][2]);
            acc[0][3] = fmaf(a.x, b.w, acc[0][3]);
            acc[1][0] = fmaf(a.y, b.x, acc[1][0]);
            acc[1][1] = fmaf(a.y, b.y, acc[1][1]);
            acc[1][2] = fmaf(a.y, b.z, acc[1][2]);
            acc[1][3] = fmaf(a.y, b.w, acc[1][3]);
        }
        __syncthreads();
    }

#pragma unroll
    for (int i = 0; i < 2; i++) {
        int gm = bm + tr * 2 + i;
        if (gm >= M) continue;
#pragma unroll
        for (int j = 0; j < 4; j++) {
            int gn = bn + tc * 4 + j;
            if (gn >= Ncols) continue;
            float bv = bias ? bias[gn] : 0.f;
            C[(long)gm * Ncols + gn] = acc[i][j] + bv;
        }
    }
}

// ---------------- cross attention + sentence gate -> f_bq ----------------
// block per (b,n), 640 threads (20 warps: warp w computes logit w).
__global__ void cross_attn_kernel(const float* __restrict__ q,
                                  const float* __restrict__ k,
                                  const float* __restrict__ f_w,
                                  const float* __restrict__ f_b,
                                  const float* __restrict__ f_s,
                                  float* __restrict__ fbq)
{
    int n = blockIdx.x, b = blockIdx.y;
    int row = b * Nn + n;
    __shared__ float qs[Dd];
    __shared__ float sl[Ll];
    int t = threadIdx.x;
    if (t < Dd) qs[t] = q[(long)row * Dd + t];
    __syncthreads();

    int w = t >> 5, lane = t & 31;
    if (w < Ll) {
        const float* kr = k + (long)(b * Ll + w) * Dd;
        float p = 0.f;
#pragma unroll
        for (int d = 0; d < Dd / 32; d++) p = fmaf(qs[lane + d * 32], kr[lane + d * 32], p);
#pragma unroll
        for (int off = 16; off > 0; off >>= 1) p += __shfl_xor_sync(0xffffffff, p, off);
        if (lane == 0) sl[w] = p;
    }
    __syncthreads();

    if (t < Dd) {
        float z[Ll];
        float mx = -1e30f;
#pragma unroll
        for (int l = 0; l < Ll; l++) { z[l] = sl[l] * SCALE; mx = fmaxf(mx, z[l]); }
        float den = 0.f, accq = 0.f;
#pragma unroll
        for (int l = 0; l < Ll; l++) {
            float e = __expf(z[l] - mx);
            den += e;
            accq = fmaf(e, f_w[(long)(b * Ll + l) * Dd + t], accq);
        }
        float fbaq = accq / den;
        float v = f_b[(long)row * Dd + t] * (fbaq + f_s[(long)b * Dd + t]);
        fbq[(long)row * Dd + t] = v;
    }
}

// ---------------- row softmax of S (scaled), in place ----------------
// 4 warps / block, warp per row. 128 blocks -> 512 rows of 128 cols.
__global__ void softmax_rows_kernel(float* __restrict__ S)
{
    int warp = threadIdx.x >> 5, lane = threadIdx.x & 31;
    int row = blockIdx.x * 4 + warp;
    float v[4];
    float mx = -1e30f;
#pragma unroll
    for (int j = 0; j < 4; j++) {
        v[j] = S[(long)row * Nn + lane + j * 32] * SCALE;
        mx = fmaxf(mx, v[j]);
    }
#pragma unroll
    for (int off = 16; off > 0; off >>= 1) mx = fmaxf(mx, __shfl_xor_sync(0xffffffff, mx, off));
    float sum = 0.f;
#pragma unroll
    for (int j = 0; j < 4; j++) { v[j] = __expf(v[j] - mx); sum += v[j]; }
#pragma unroll
    for (int off = 16; off > 0; off >>= 1) sum += __shfl_xor_sync(0xffffffff, sum, off);
    float inv = __fdividef(1.f, sum);
#pragma unroll
    for (int j = 0; j < 4; j++) S[(long)row * Nn + lane + j * 32] = v[j] * inv;
}

// ---------------- fused f_bb + residual + gated moment reduction ----------------
// block per (b,j), 512 threads (one per d). f_m streamed exactly once.
__global__ void moment_kernel(const float* __restrict__ Ab,
                              const float* __restrict__ f_b,
                              const float* __restrict__ f_m,
                              const float* __restrict__ f_s,
                              float* __restrict__ out)
{
    int j = blockIdx.x, b = blockIdx.y;
    int d = threadIdx.x;
    __shared__ float Acol[Nn];  // A_b[b, i, j] over i
    __shared__ float Arow[Nn];  // A_b[b, j, m] over m
    if (d < Nn) {
        Acol[d] = Ab[(long)(b * Nn + d) * Nn + j];
        Arow[d] = Ab[(long)(b * Nn + j) * Nn + d];
    }
    __syncthreads();

    float s = f_s[(long)b * Dd + d];
    const float* fm = f_m + ((long)(b * Nn) * Nn + j) * Dd + d;  // + i*Nn*Dd
    const float* fb = f_b + (long)b * Nn * Dd + d;               // + i*Dd

    float accm = 0.f, accb = 0.f;
#pragma unroll 4
    for (int i = 0; i < Nn; i++) {
        float x  = fm[(long)i * Nn * Dd];
        float fv = fb[(long)i * Dd];
        float e   = __expf(-x * s);
        float sig = __fdividef(1.f, 1.f + e);
        accm = fmaf(Acol[i] * x, sig, accm);
        accb = fmaf(Arow[i], fv, accb);
    }
    out[(long)(b * Nn + j) * Dd + d] = accb + fb[(long)j * Dd] + accm;
}

// ---------------- launch ----------------
extern "C" void kernel_launch(void* const* d_in, const int* in_sizes, int n_in,
                              void* d_out, int out_size)
{
    const float* f_b = (const float*)d_in[0];
    const float* f_w = (const float*)d_in[1];
    const float* f_s = (const float*)d_in[2];
    const float* f_m = (const float*)d_in[3];
    const float* Wq  = (const float*)d_in[4];
    const float* bq  = (const float*)d_in[5];
    const float* Wk  = (const float*)d_in[6];
    const float* bk  = (const float*)d_in[7];
    float* out = (float*)d_out;

    float* q   = nullptr; cudaGetSymbolAddress((void**)&q,   g_q);
    float* kk  = nullptr; cudaGetSymbolAddress((void**)&kk,  g_k);
    float* fbq = nullptr; cudaGetSymbolAddress((void**)&fbq, g_fbq);
    float* S   = nullptr; cudaGetSymbolAddress((void**)&S,   g_S);

    // 1) q = f_b @ Wq^T + bq   [512,512]
    {
        dim3 grid(Dd / BN, (Bb * Nn + BM - 1) / BM, 1);
        gemm_nt<<<grid, 256>>>(f_b, Wq, bq, q, Bb * Nn, Dd, Dd, 0, 0, 0);
    }
    // 2) k = f_w @ Wk^T + bk   [80,512]
    {
        dim3 grid(Dd / BN, (Bb * Ll + BM - 1) / BM, 1);
        gemm_nt<<<grid, 256>>>(f_w, Wk, bk, kk, Bb * Ll, Dd, Dd, 0, 0, 0);
    }
    // 3) cross attention + gate -> f_bq
    {
        dim3 grid(Nn, Bb);
        cross_attn_kernel<<<grid, 640>>>(q, kk, f_w, f_b, f_s, fbq);
    }
    // 4) S = f_bq @ f_bq^T per batch  [4,128,128]
    {
        dim3 grid(Nn / BN, Nn / BM, Bb);
        gemm_nt<<<grid, 256>>>(fbq, fbq, nullptr, S, Nn, Nn, Dd,
                               Nn * Dd, Nn * Dd, Nn * Nn);
    }
    // 5) softmax rows of S -> A_b (in place)
    softmax_rows_kernel<<<(Bb * Nn) / 4, 128>>>(S);
    // 6) fused f_bb + f_b + f_bm
    {
        dim3 grid(Nn, Bb);
        moment_kernel<<<grid, 512>>>(S, f_b, f_m, f_s, out);
    }
    (void)in_sizes; (void)n_in; (void)out_size;
}

// round 4
// speedup vs baseline: 1.1650x; 1.1650x over previous
#include <cuda_runtime.h>
#include <math.h>

#define Bb 4
#define Nn 128
#define Ll 20
#define Dd 512
#define SCALE 0.044194173824159216f  // 1/sqrt(512)
#define KS 4                          // split-K factor for S GEMM
#define KCH (Dd / KS)                 // 128

// ---------------- scratch (no allocations allowed) ----------------
__device__ float g_k  [Bb*Ll*Dd];        // k = f_w Wk^T + bk        [80,512]
__device__ float g_u  [Bb*Ll*Dd];        // u = k Wq                 [80,512]
__device__ float g_fbq[Bb*Nn*Dd];        // gated boundary feats     [512,512]
__device__ float g_S  [Bb*Nn*Nn];        // A_b after softmax        [4,128,128]
__device__ float g_Sp [KS*Bb*Nn*Nn];     // split-K partials of S

__device__ __forceinline__ float tanh_approx(float x) {
    float y; asm("tanh.approx.f32 %0, %1;" : "=f"(y) : "f"(x)); return y;
}

// ---------------- NT GEMM: C[M,N] = A[M,K] * B[N,K]^T (+bias) ----
#define BM 32
#define BN 64
#define BK 32

__global__ void gemm_nt(const float* __restrict__ A, const float* __restrict__ Bmat,
                        const float* __restrict__ bias, float* __restrict__ C,
                        int M, int Ncols, int K)
{
    int bm = blockIdx.y * BM;
    int bn = blockIdx.x * BN;

    __shared__ float Ast[BK][BM + 2];   // stride 34 (even) -> float2 aligned
    __shared__ float Bst[BK][BN + 4];   // stride 68 -> float4 aligned

    int tid = threadIdx.x;
    int tr  = tid >> 4;
    int tc  = tid & 15;

    float acc[2][4];
#pragma unroll
    for (int i = 0; i < 2; i++)
#pragma unroll
        for (int j = 0; j < 4; j++) acc[i][j] = 0.f;

    int arow = tid >> 3;
    int acol = (tid & 7) * 4;
    int brow0 = tid >> 3;
    int brow1 = brow0 + 32;

    for (int k0 = 0; k0 < K; k0 += BK) {
        float4 av = make_float4(0.f, 0.f, 0.f, 0.f);
        int gm = bm + arow;
        if (gm < M) av = *(const float4*)(A + (long)gm * K + k0 + acol);
        Ast[acol + 0][arow] = av.x;
        Ast[acol + 1][arow] = av.y;
        Ast[acol + 2][arow] = av.z;
        Ast[acol + 3][arow] = av.w;
        float4 bv0 = *(const float4*)(Bmat + (long)(bn + brow0) * K + k0 + acol);
        float4 bv1 = *(const float4*)(Bmat + (long)(bn + brow1) * K + k0 + acol);
        Bst[acol + 0][brow0] = bv0.x;
        Bst[acol + 1][brow0] = bv0.y;
        Bst[acol + 2][brow0] = bv0.z;
        Bst[acol + 3][brow0] = bv0.w;
        Bst[acol + 0][brow1] = bv1.x;
        Bst[acol + 1][brow1] = bv1.y;
        Bst[acol + 2][brow1] = bv1.z;
        Bst[acol + 3][brow1] = bv1.w;
        __syncthreads();

#pragma unroll
        for (int k = 0; k < BK; k++) {
            float2 a = *(const float2*)&Ast[k][tr * 2];
            float4 b = *(const float4*)&Bst[k][tc * 4];
            acc[0][0] = fmaf(a.x, b.x, acc[0][0]);
            acc[0][1] = fmaf(a.x, b.y, acc[0][1]);
            acc[0][2] = fmaf(a.x, b.z, acc[0][2]);
            acc[0][3] = fmaf(a.x, b.w, acc[0][3]);
            acc[1][0] = fmaf(a.y, b.x, acc[1][0]);
            acc[1][1] = fmaf(a.y, b.y, acc[1][1]);
            acc[1][2] = fmaf(a.y, b.z, acc[1][2]);
            acc[1][3] = fmaf(a.y, b.w, acc[1][3]);
        }
        __syncthreads();
    }

#pragma unroll
    for (int i = 0; i < 2; i++) {
        int gm = bm + tr * 2 + i;
        if (gm >= M) continue;
#pragma unroll
        for (int j = 0; j < 4; j++) {
            int gn = bn + tc * 4 + j;
            float bv = bias ? bias[gn] : 0.f;
            C[(long)gm * Ncols + gn] = acc[i][j] + bv;
        }
    }
}

// ---------------- NN GEMM: C[M,N] = A[M,K] * B[K,N] ----------------
__global__ void gemm_nn(const float* __restrict__ A, const float* __restrict__ Bmat,
                        float* __restrict__ C, int M, int Ncols, int K)
{
    int bm = blockIdx.y * BM;
    int bn = blockIdx.x * BN;

    __shared__ float Ast[BK][BM + 2];
    __shared__ float Bst[BK][BN + 4];

    int tid = threadIdx.x;
    int tr  = tid >> 4;
    int tc  = tid & 15;

    float acc[2][4];
#pragma unroll
    for (int i = 0; i < 2; i++)
#pragma unroll
        for (int j = 0; j < 4; j++) acc[i][j] = 0.f;

    int arow = tid >> 3;
    int acol = (tid & 7) * 4;
    int bkrow = tid >> 4;          // 0..15
    int bncol = (tid & 15) * 4;    // 0..60

    for (int k0 = 0; k0 < K; k0 += BK) {
        float4 av = make_float4(0.f, 0.f, 0.f, 0.f);
        int gm = bm + arow;
        if (gm < M) av = *(const float4*)(A + (long)gm * K + k0 + acol);
        Ast[acol + 0][arow] = av.x;
        Ast[acol + 1][arow] = av.y;
        Ast[acol + 2][arow] = av.z;
        Ast[acol + 3][arow] = av.w;
#pragma unroll
        for (int p = 0; p < 2; p++) {
            int krow = bkrow + p * 16;
            float4 bv = *(const float4*)(Bmat + (long)(k0 + krow) * Ncols + bn + bncol);
            *(float4*)&Bst[krow][bncol] = bv;
        }
        __syncthreads();

#pragma unroll
        for (int k = 0; k < BK; k++) {
            float2 a = *(const float2*)&Ast[k][tr * 2];
            float4 b = *(const float4*)&Bst[k][tc * 4];
            acc[0][0] = fmaf(a.x, b.x, acc[0][0]);
            acc[0][1] = fmaf(a.x, b.y, acc[0][1]);
            acc[0][2] = fmaf(a.x, b.z, acc[0][2]);
            acc[0][3] = fmaf(a.x, b.w, acc[0][3]);
            acc[1][0] = fmaf(a.y, b.x, acc[1][0]);
            acc[1][1] = fmaf(a.y, b.y, acc[1][1]);
            acc[1][2] = fmaf(a.y, b.z, acc[1][2]);
            acc[1][3] = fmaf(a.y, b.w, acc[1][3]);
        }
        __syncthreads();
    }

#pragma unroll
    for (int i = 0; i < 2; i++) {
        int gm = bm + tr * 2 + i;
        if (gm >= M) continue;
#pragma unroll
        for (int j = 0; j < 4; j++) {
            int gn = bn + tc * 4 + j;
            C[(long)gm * Ncols + gn] = acc[i][j];
        }
    }
}

// ------- cross attention + sentence gate -> f_bq (uses u instead of q) -------
// logit[b,n,l] = f_b[b,n].u[b,l] + bq.k[b,l]
__global__ void cross_attn_kernel(const float* __restrict__ u,
                                  const float* __restrict__ k,
                                  const float* __restrict__ bq,
                                  const float* __restrict__ f_w,
                                  const float* __restrict__ f_b,
                                  const float* __restrict__ f_s,
                                  float* __restrict__ fbq)
{
    int n = blockIdx.x, b = blockIdx.y;
    int row = b * Nn + n;
    __shared__ float qs[Dd];
    __shared__ float sl[Ll];
    int t = threadIdx.x;
    if (t < Dd) qs[t] = f_b[(long)row * Dd + t];
    __syncthreads();

    int w = t >> 5, lane = t & 31;
    if (w < Ll) {
        const float* ur = u + (long)(b * Ll + w) * Dd;
        const float* kr = k + (long)(b * Ll + w) * Dd;
        float p = 0.f;
#pragma unroll
        for (int d = 0; d < Dd / 32; d++) {
            int idx = lane + d * 32;
            p = fmaf(qs[idx], ur[idx], p);
            p = fmaf(bq[idx], kr[idx], p);
        }
#pragma unroll
        for (int off = 16; off > 0; off >>= 1) p += __shfl_xor_sync(0xffffffff, p, off);
        if (lane == 0) sl[w] = p;
    }
    __syncthreads();

    if (t < Dd) {
        float z[Ll];
        float mx = -1e30f;
#pragma unroll
        for (int l = 0; l < Ll; l++) { z[l] = sl[l] * SCALE; mx = fmaxf(mx, z[l]); }
        float den = 0.f, accq = 0.f;
#pragma unroll
        for (int l = 0; l < Ll; l++) {
            float e = __expf(z[l] - mx);
            den += e;
            accq = fmaf(e, f_w[(long)(b * Ll + l) * Dd + t], accq);
        }
        float fbaq = accq / den;
        float v = f_b[(long)row * Dd + t] * (fbaq + f_s[(long)b * Dd + t]);
        fbq[(long)row * Dd + t] = v;
    }
}

// -------- S split-K GEMM: Sp[s][b][m][n] = sum_{k in chunk s} fbq[b,m,k]*fbq[b,n,k] ----
// grid: x=4 (n tiles of 32), y=4 (m tiles of 32), z = b*KS + s. 256 threads, 2x2 tile.
__global__ void s_gemm_kernel(const float* __restrict__ fbq, float* __restrict__ Sp)
{
    int b = blockIdx.z / KS;
    int s = blockIdx.z % KS;
    const float* A = fbq + (long)b * Nn * Dd;
    int bm = blockIdx.y * 32;
    int bn = blockIdx.x * 32;
    int kbase = s * KCH;

    __shared__ float Ast[32][34];   // EVEN stride -> float2 reads stay 8B-aligned
    __shared__ float Bst[32][34];

    int tid = threadIdx.x;
    int tr = tid >> 4, tc = tid & 15;
    int arow = tid >> 3;
    int acol = (tid & 7) * 4;

    float a00 = 0.f, a01 = 0.f, a10 = 0.f, a11 = 0.f;

    for (int k0 = 0; k0 < KCH; k0 += 32) {
        float4 av = *(const float4*)(A + (long)(bm + arow) * Dd + kbase + k0 + acol);
        Ast[acol + 0][arow] = av.x;
        Ast[acol + 1][arow] = av.y;
        Ast[acol + 2][arow] = av.z;
        Ast[acol + 3][arow] = av.w;
        float4 bv = *(const float4*)(A + (long)(bn + arow) * Dd + kbase + k0 + acol);
        Bst[acol + 0][arow] = bv.x;
        Bst[acol + 1][arow] = bv.y;
        Bst[acol + 2][arow] = bv.z;
        Bst[acol + 3][arow] = bv.w;
        __syncthreads();
#pragma unroll
        for (int k = 0; k < 32; k++) {
            float2 a = *(const float2*)&Ast[k][tr * 2];
            float2 bb = *(const float2*)&Bst[k][tc * 2];
            a00 = fmaf(a.x, bb.x, a00);
            a01 = fmaf(a.x, bb.y, a01);
            a10 = fmaf(a.y, bb.x, a10);
            a11 = fmaf(a.y, bb.y, a11);
        }
        __syncthreads();
    }

    float* o = Sp + ((long)(s * Bb + b) * Nn) * Nn;
    int gm = bm + tr * 2, gn = bn + tc * 2;
    o[(long)gm * Nn + gn]           = a00;
    o[(long)gm * Nn + gn + 1]       = a01;
    o[(long)(gm + 1) * Nn + gn]     = a10;
    o[(long)(gm + 1) * Nn + gn + 1] = a11;
}

// -------- reduce split-K partials + row softmax -> A_b ----------------
// warp per row (r in [0, B*N)), 4 warps/block.
__global__ void softmax_reduce_kernel(const float* __restrict__ Sp, float* __restrict__ S)
{
    int warp = threadIdx.x >> 5, lane = threadIdx.x & 31;
    int r = blockIdx.x * 4 + warp;       // r = b*Nn + m
    int bidx = r >> 7;                   // batch (r / Nn)
    int m = r & (Nn - 1);
    float v[4];
#pragma unroll
    for (int j = 0; j < 4; j++) {
        int col = lane + j * 32;
        float sum = 0.f;
#pragma unroll
        for (int s = 0; s < KS; s++)
            sum += Sp[((long)(s * Bb + bidx) * Nn + m) * Nn + col];
        v[j] = sum * SCALE;
    }
    float mx = fmaxf(fmaxf(v[0], v[1]), fmaxf(v[2], v[3]));
#pragma unroll
    for (int off = 16; off > 0; off >>= 1) mx = fmaxf(mx, __shfl_xor_sync(0xffffffff, mx, off));
    float sum = 0.f;
#pragma unroll
    for (int j = 0; j < 4; j++) { v[j] = __expf(v[j] - mx); sum += v[j]; }
#pragma unroll
    for (int off = 16; off > 0; off >>= 1) sum += __shfl_xor_sync(0xffffffff, sum, off);
    float inv = __fdividef(1.f, sum);
#pragma unroll
    for (int j = 0; j < 4; j++) S[(long)r * Nn + lane + j * 32] = v[j] * inv;
}

// -------- fused f_bb + residual + gated moment reduction ----------------
// block per (b,j), 512 threads (one per d). f_m streamed exactly once.
__global__ void moment_kernel(const float* __restrict__ Ab,
                              const float* __restrict__ f_b,
                              const float* __restrict__ f_m,
                              const float* __restrict__ f_s,
                              float* __restrict__ out)
{
    int j = blockIdx.x, b = blockIdx.y;
    int d = threadIdx.x;
    __shared__ float Acol[Nn];   // A_b[b, i, j] over i
    __shared__ float Arow[Nn];   // A_b[b, j, m] over m
    if (d < Nn) {
        Acol[d] = Ab[(long)(b * Nn + d) * Nn + j];
        Arow[d] = Ab[(long)(b * Nn + j) * Nn + d];
    }
    __syncthreads();

    float s  = f_s[(long)b * Dd + d];
    float hs = 0.5f * s;
    const float* fm = f_m + ((long)(b * Nn) * Nn + j) * Dd + d;   // + i*Nn*Dd
    const float* fb = f_b + (long)b * Nn * Dd + d;                // + i*Dd

    float accm = 0.f, accb = 0.f;
#pragma unroll 8
    for (int i = 0; i < Nn; i++) {
        float x  = fm[(long)i * Nn * Dd];
        float fv = fb[(long)i * Dd];
        float t   = tanh_approx(x * hs);
        float sig = fmaf(t, 0.5f, 0.5f);     // sigmoid(x*s)
        accm = fmaf(Acol[i] * x, sig, accm);
        accb = fmaf(Arow[i], fv, accb);
    }
    out[(long)(b * Nn + j) * Dd + d] = accb + fb[(long)j * Dd] + accm;
}

// ---------------- launch ----------------
extern "C" void kernel_launch(void* const* d_in, const int* in_sizes, int n_in,
                              void* d_out, int out_size)
{
    const float* f_b = (const float*)d_in[0];
    const float* f_w = (const float*)d_in[1];
    const float* f_s = (const float*)d_in[2];
    const float* f_m = (const float*)d_in[3];
    const float* Wq  = (const float*)d_in[4];
    const float* bq  = (const float*)d_in[5];
    const float* Wk  = (const float*)d_in[6];
    const float* bk  = (const float*)d_in[7];
    float* out = (float*)d_out;

    float* kk  = nullptr; cudaGetSymbolAddress((void**)&kk,  g_k);
    float* u   = nullptr; cudaGetSymbolAddress((void**)&u,   g_u);
    float* fbq = nullptr; cudaGetSymbolAddress((void**)&fbq, g_fbq);
    float* S   = nullptr; cudaGetSymbolAddress((void**)&S,   g_S);
    float* Sp  = nullptr; cudaGetSymbolAddress((void**)&Sp,  g_Sp);

    // 1) k = f_w @ Wk^T + bk   [80,512]
    {
        dim3 grid(Dd / BN, (Bb * Ll + BM - 1) / BM);
        gemm_nt<<<grid, 256>>>(f_w, Wk, bk, kk, Bb * Ll, Dd, Dd);
    }
    // 2) u = k @ Wq            [80,512]   (so logits = f_b.u + bq.k)
    {
        dim3 grid(Dd / BN, (Bb * Ll + BM - 1) / BM);
        gemm_nn<<<grid, 256>>>(kk, Wq, u, Bb * Ll, Dd, Dd);
    }
    // 3) cross attention + gate -> f_bq
    {
        dim3 grid(Nn, Bb);
        cross_attn_kernel<<<grid, 640>>>(u, kk, bq, f_w, f_b, f_s, fbq);
    }
    // 4) S partials = split-K f_bq @ f_bq^T per batch
    {
        dim3 grid(Nn / 32, Nn / 32, Bb * KS);
        s_gemm_kernel<<<grid, 256>>>(fbq, Sp);
    }
    // 5) reduce partials + softmax -> A_b
    softmax_reduce_kernel<<<(Bb * Nn) / 4, 128>>>(Sp, S);
    // 6) fused f_bb + f_b + f_bm
    {
        dim3 grid(Nn, Bb);
        moment_kernel<<<grid, 512>>>(S, f_b, f_m, f_s, out);
    }
    (void)in_sizes; (void)n_in; (void)out_size;
}

// round 5
// speedup vs baseline: 1.2143x; 1.0423x over previous
#include <cuda_runtime.h>
#include <math.h>

#define Bb 4
#define Nn 128
#define Ll 20
#define Dd 512
#define SCALE 0.044194173824159216f  // 1/sqrt(512)
#define KS 4                          // split-K factor for S GEMM
#define KCH (Dd / KS)                 // 128

// ---------------- scratch (no allocations allowed) ----------------
__device__ float g_k  [Bb*Ll*Dd];        // k = f_w Wk^T + bk        [80,512]
__device__ float g_u  [Bb*Ll*Dd];        // u = k Wq                 [80,512]
__device__ float g_fbq[Bb*Nn*Dd];        // gated boundary feats     [512,512]
__device__ float g_S  [Bb*Nn*Nn];        // A_b after softmax        [4,128,128]
__device__ float g_Sp [KS*Bb*Nn*Nn];     // split-K partials of S
__device__ float g_fbb[Bb*Nn*Dd];        // A_b @ f_b + f_b          [4,128,512]

__device__ __forceinline__ float tanh_approx(float x) {
    float y; asm("tanh.approx.f32 %0, %1;" : "=f"(y) : "f"(x)); return y;
}

// ======== 16-row NT GEMM with double-buffered smem: C[80,512] = A[80,512] B[512,512]^T (+bias)
__global__ void gemm_nt16(const float* __restrict__ A, const float* __restrict__ Bm,
                          const float* __restrict__ bias, float* __restrict__ C)
{
    const int K = Dd;
    int bm = blockIdx.y * 16;
    int bn = blockIdx.x * 64;

    __shared__ float Ast[2][32][18];
    __shared__ float Bst[2][32][68];

    int tid = threadIdx.x;
    int tr = tid >> 4, tc = tid & 15;
    int arow = tid >> 3;          // for tid<128: 0..15
    int acol = (tid & 7) * 4;
    int brow0 = tid >> 3;         // 0..31
    int brow1 = brow0 + 32;

    float4 av = make_float4(0.f,0.f,0.f,0.f), bv0, bv1;
    if (tid < 128) av = *(const float4*)(A + (long)(bm + arow) * K + acol);
    bv0 = *(const float4*)(Bm + (long)(bn + brow0) * K + acol);
    bv1 = *(const float4*)(Bm + (long)(bn + brow1) * K + acol);
    if (tid < 128) {
        Ast[0][acol+0][arow]=av.x; Ast[0][acol+1][arow]=av.y;
        Ast[0][acol+2][arow]=av.z; Ast[0][acol+3][arow]=av.w;
    }
    Bst[0][acol+0][brow0]=bv0.x; Bst[0][acol+1][brow0]=bv0.y;
    Bst[0][acol+2][brow0]=bv0.z; Bst[0][acol+3][brow0]=bv0.w;
    Bst[0][acol+0][brow1]=bv1.x; Bst[0][acol+1][brow1]=bv1.y;
    Bst[0][acol+2][brow1]=bv1.z; Bst[0][acol+3][brow1]=bv1.w;
    __syncthreads();

    float acc0=0.f, acc1=0.f, acc2=0.f, acc3=0.f;
    const int nit = K / 32;
    int buf = 0;
    for (int it = 0; it < nit; it++) {
        bool more = (it + 1 < nit);
        if (more) {
            int k0n = (it + 1) * 32;
            if (tid < 128) av = *(const float4*)(A + (long)(bm + arow) * K + k0n + acol);
            bv0 = *(const float4*)(Bm + (long)(bn + brow0) * K + k0n + acol);
            bv1 = *(const float4*)(Bm + (long)(bn + brow1) * K + k0n + acol);
        }
#pragma unroll
        for (int k = 0; k < 32; k++) {
            float a = Ast[buf][k][tr];
            float4 b = *(const float4*)&Bst[buf][k][tc * 4];
            acc0 = fmaf(a, b.x, acc0);
            acc1 = fmaf(a, b.y, acc1);
            acc2 = fmaf(a, b.z, acc2);
            acc3 = fmaf(a, b.w, acc3);
        }
        if (more) {
            int nb = buf ^ 1;
            if (tid < 128) {
                Ast[nb][acol+0][arow]=av.x; Ast[nb][acol+1][arow]=av.y;
                Ast[nb][acol+2][arow]=av.z; Ast[nb][acol+3][arow]=av.w;
            }
            Bst[nb][acol+0][brow0]=bv0.x; Bst[nb][acol+1][brow0]=bv0.y;
            Bst[nb][acol+2][brow0]=bv0.z; Bst[nb][acol+3][brow0]=bv0.w;
            Bst[nb][acol+0][brow1]=bv1.x; Bst[nb][acol+1][brow1]=bv1.y;
            Bst[nb][acol+2][brow1]=bv1.z; Bst[nb][acol+3][brow1]=bv1.w;
            __syncthreads();
            buf = nb;
        }
    }

    int gm = bm + tr;
    int gn = bn + tc * 4;
    float4 bb = bias ? *(const float4*)(bias + gn) : make_float4(0.f,0.f,0.f,0.f);
    C[(long)gm * Dd + gn + 0] = acc0 + bb.x;
    C[(long)gm * Dd + gn + 1] = acc1 + bb.y;
    C[(long)gm * Dd + gn + 2] = acc2 + bb.z;
    C[(long)gm * Dd + gn + 3] = acc3 + bb.w;
}

// ======== 16-row NN GEMM with double buffering: C[80,512] = A[80,512] B[512,512]
__global__ void gemm_nn16(const float* __restrict__ A, const float* __restrict__ Bm,
                          float* __restrict__ C)
{
    const int K = Dd;
    int bm = blockIdx.y * 16;
    int bn = blockIdx.x * 64;

    __shared__ float Ast[2][32][18];
    __shared__ float Bst[2][32][68];

    int tid = threadIdx.x;
    int tr = tid >> 4, tc = tid & 15;
    int arow = tid >> 3;
    int acol = (tid & 7) * 4;
    int bkr0 = tid >> 4;          // 0..15
    int bkr1 = bkr0 + 16;
    int bcol = (tid & 15) * 4;

    float4 av = make_float4(0.f,0.f,0.f,0.f), bv0, bv1;
    if (tid < 128) av = *(const float4*)(A + (long)(bm + arow) * K + acol);
    bv0 = *(const float4*)(Bm + (long)bkr0 * Dd + bn + bcol);
    bv1 = *(const float4*)(Bm + (long)bkr1 * Dd + bn + bcol);
    if (tid < 128) {
        Ast[0][acol+0][arow]=av.x; Ast[0][acol+1][arow]=av.y;
        Ast[0][acol+2][arow]=av.z; Ast[0][acol+3][arow]=av.w;
    }
    *(float4*)&Bst[0][bkr0][bcol] = bv0;
    *(float4*)&Bst[0][bkr1][bcol] = bv1;
    __syncthreads();

    float acc0=0.f, acc1=0.f, acc2=0.f, acc3=0.f;
    const int nit = K / 32;
    int buf = 0;
    for (int it = 0; it < nit; it++) {
        bool more = (it + 1 < nit);
        if (more) {
            int k0n = (it + 1) * 32;
            if (tid < 128) av = *(const float4*)(A + (long)(bm + arow) * K + k0n + acol);
            bv0 = *(const float4*)(Bm + (long)(k0n + bkr0) * Dd + bn + bcol);
            bv1 = *(const float4*)(Bm + (long)(k0n + bkr1) * Dd + bn + bcol);
        }
#pragma unroll
        for (int k = 0; k < 32; k++) {
            float a = Ast[buf][k][tr];
            float4 b = *(const float4*)&Bst[buf][k][tc * 4];
            acc0 = fmaf(a, b.x, acc0);
            acc1 = fmaf(a, b.y, acc1);
            acc2 = fmaf(a, b.z, acc2);
            acc3 = fmaf(a, b.w, acc3);
        }
        if (more) {
            int nb = buf ^ 1;
            if (tid < 128) {
                Ast[nb][acol+0][arow]=av.x; Ast[nb][acol+1][arow]=av.y;
                Ast[nb][acol+2][arow]=av.z; Ast[nb][acol+3][arow]=av.w;
            }
            *(float4*)&Bst[nb][bkr0][bcol] = bv0;
            *(float4*)&Bst[nb][bkr1][bcol] = bv1;
            __syncthreads();
            buf = nb;
        }
    }

    int gm = bm + tr;
    int gn = bn + tc * 4;
    C[(long)gm * Dd + gn + 0] = acc0;
    C[(long)gm * Dd + gn + 1] = acc1;
    C[(long)gm * Dd + gn + 2] = acc2;
    C[(long)gm * Dd + gn + 3] = acc3;
}

// ------- cross attention + sentence gate -> f_bq (uses u instead of q) -------
// logit[b,n,l] = f_b[b,n].u[b,l] + bq.k[b,l]
__global__ void cross_attn_kernel(const float* __restrict__ u,
                                  const float* __restrict__ k,
                                  const float* __restrict__ bq,
                                  const float* __restrict__ f_w,
                                  const float* __restrict__ f_b,
                                  const float* __restrict__ f_s,
                                  float* __restrict__ fbq)
{
    int n = blockIdx.x, b = blockIdx.y;
    int row = b * Nn + n;
    __shared__ float qs[Dd];
    __shared__ float sl[Ll];
    int t = threadIdx.x;
    if (t < Dd) qs[t] = f_b[(long)row * Dd + t];
    __syncthreads();

    int w = t >> 5, lane = t & 31;
    if (w < Ll) {
        const float* ur = u + (long)(b * Ll + w) * Dd;
        const float* kr = k + (long)(b * Ll + w) * Dd;
        float p = 0.f;
#pragma unroll
        for (int d = 0; d < Dd / 32; d++) {
            int idx = lane + d * 32;
            p = fmaf(qs[idx], ur[idx], p);
            p = fmaf(bq[idx], kr[idx], p);
        }
#pragma unroll
        for (int off = 16; off > 0; off >>= 1) p += __shfl_xor_sync(0xffffffff, p, off);
        if (lane == 0) sl[w] = p;
    }
    __syncthreads();

    if (t < Dd) {
        float z[Ll];
        float mx = -1e30f;
#pragma unroll
        for (int l = 0; l < Ll; l++) { z[l] = sl[l] * SCALE; mx = fmaxf(mx, z[l]); }
        float den = 0.f, accq = 0.f;
#pragma unroll
        for (int l = 0; l < Ll; l++) {
            float e = __expf(z[l] - mx);
            den += e;
            accq = fmaf(e, f_w[(long)(b * Ll + l) * Dd + t], accq);
        }
        float fbaq = accq / den;
        float v = f_b[(long)row * Dd + t] * (fbaq + f_s[(long)b * Dd + t]);
        fbq[(long)row * Dd + t] = v;
    }
}

// -------- S split-K GEMM, single-sync: load full 32x128 K-chunks into smem ----
// grid: x=4 (n tiles 32), y=4 (m tiles 32), z = b*KS + s. 256 threads, 2x2 tile.
__global__ void s_gemm_kernel(const float* __restrict__ fbq, float* __restrict__ Sp)
{
    int b = blockIdx.z / KS;
    int s = blockIdx.z % KS;
    const float* A = fbq + (long)b * Nn * Dd;
    int bm = blockIdx.y * 32;
    int bn = blockIdx.x * 32;
    int kbase = s * KCH;

    __shared__ float As[KCH][34];   // [k][m], even stride -> float2 aligned
    __shared__ float Bs[KCH][34];

    int tid = threadIdx.x;
    int arow = tid >> 3;            // 0..31
    int ac   = (tid & 7) * 4;

#pragma unroll
    for (int q = 0; q < 4; q++) {
        int col = ac + q * 32;
        float4 av = *(const float4*)(A + (long)(bm + arow) * Dd + kbase + col);
        As[col+0][arow]=av.x; As[col+1][arow]=av.y; As[col+2][arow]=av.z; As[col+3][arow]=av.w;
        float4 bv = *(const float4*)(A + (long)(bn + arow) * Dd + kbase + col);
        Bs[col+0][arow]=bv.x; Bs[col+1][arow]=bv.y; Bs[col+2][arow]=bv.z; Bs[col+3][arow]=bv.w;
    }
    __syncthreads();

    int tr = tid >> 4, tc = tid & 15;
    float a00=0.f, a01=0.f, a10=0.f, a11=0.f;
#pragma unroll 8
    for (int k = 0; k < KCH; k++) {
        float2 a  = *(const float2*)&As[k][tr * 2];
        float2 bb = *(const float2*)&Bs[k][tc * 2];
        a00 = fmaf(a.x, bb.x, a00);
        a01 = fmaf(a.x, bb.y, a01);
        a10 = fmaf(a.y, bb.x, a10);
        a11 = fmaf(a.y, bb.y, a11);
    }

    float* o = Sp + ((long)(s * Bb + b) * Nn) * Nn;
    int gm = bm + tr * 2, gn = bn + tc * 2;
    o[(long)gm * Nn + gn]           = a00;
    o[(long)gm * Nn + gn + 1]       = a01;
    o[(long)(gm + 1) * Nn + gn]     = a10;
    o[(long)(gm + 1) * Nn + gn + 1] = a11;
}

// -------- reduce split-K partials + row softmax -> A_b ----------------
__global__ void softmax_reduce_kernel(const float* __restrict__ Sp, float* __restrict__ S)
{
    int warp = threadIdx.x >> 5, lane = threadIdx.x & 31;
    int r = blockIdx.x * 4 + warp;       // r = b*Nn + m
    int bidx = r >> 7;
    int m = r & (Nn - 1);
    float v[4];
#pragma unroll
    for (int j = 0; j < 4; j++) {
        int col = lane + j * 32;
        float sum = 0.f;
#pragma unroll
        for (int s = 0; s < KS; s++)
            sum += Sp[((long)(s * Bb + bidx) * Nn + m) * Nn + col];
        v[j] = sum * SCALE;
    }
    float mx = fmaxf(fmaxf(v[0], v[1]), fmaxf(v[2], v[3]));
#pragma unroll
    for (int off = 16; off > 0; off >>= 1) mx = fmaxf(mx, __shfl_xor_sync(0xffffffff, mx, off));
    float sum = 0.f;
#pragma unroll
    for (int j = 0; j < 4; j++) { v[j] = __expf(v[j] - mx); sum += v[j]; }
#pragma unroll
    for (int off = 16; off > 0; off >>= 1) sum += __shfl_xor_sync(0xffffffff, sum, off);
    float inv = __fdividef(1.f, sum);
#pragma unroll
    for (int j = 0; j < 4; j++) S[(long)r * Nn + lane + j * 32] = v[j] * inv;
}

// -------- fbb = A_b @ f_b + f_b  (per batch NN GEMM, K=128) ----------------
// grid: x=8 (64-col d tiles), y=4 (32-row n tiles), z=b. 256 threads, 2x4 tile.
__global__ void fbb_gemm_kernel(const float* __restrict__ S, const float* __restrict__ f_b,
                                float* __restrict__ fbb)
{
    int b = blockIdx.z;
    const float* A  = S   + (long)b * Nn * Nn;   // [n, m] stride 128
    const float* Bf = f_b + (long)b * Nn * Dd;   // [m, d] stride 512
    int bnr = blockIdx.y * 32;    // n rows
    int bd  = blockIdx.x * 64;    // d cols

    __shared__ float Ast[32][34];
    __shared__ float Bst[32][68];

    int tid = threadIdx.x;
    int tr = tid >> 4, tc = tid & 15;
    int arow = tid >> 3;
    int acol = (tid & 7) * 4;
    int bkr0 = tid >> 4, bkr1 = bkr0 + 16;
    int bcol = (tid & 15) * 4;

    float acc[2][4];
#pragma unroll
    for (int i = 0; i < 2; i++)
#pragma unroll
        for (int j = 0; j < 4; j++) acc[i][j] = 0.f;

    for (int m0 = 0; m0 < Nn; m0 += 32) {
        float4 av = *(const float4*)(A + (long)(bnr + arow) * Nn + m0 + acol);
        Ast[acol+0][arow]=av.x; Ast[acol+1][arow]=av.y;
        Ast[acol+2][arow]=av.z; Ast[acol+3][arow]=av.w;
        *(float4*)&Bst[bkr0][bcol] = *(const float4*)(Bf + (long)(m0 + bkr0) * Dd + bd + bcol);
        *(float4*)&Bst[bkr1][bcol] = *(const float4*)(Bf + (long)(m0 + bkr1) * Dd + bd + bcol);
        __syncthreads();
#pragma unroll
        for (int k = 0; k < 32; k++) {
            float2 a = *(const float2*)&Ast[k][tr * 2];
            float4 bb = *(const float4*)&Bst[k][tc * 4];
            acc[0][0] = fmaf(a.x, bb.x, acc[0][0]);
            acc[0][1] = fmaf(a.x, bb.y, acc[0][1]);
            acc[0][2] = fmaf(a.x, bb.z, acc[0][2]);
            acc[0][3] = fmaf(a.x, bb.w, acc[0][3]);
            acc[1][0] = fmaf(a.y, bb.x, acc[1][0]);
            acc[1][1] = fmaf(a.y, bb.y, acc[1][1]);
            acc[1][2] = fmaf(a.y, bb.z, acc[1][2]);
            acc[1][3] = fmaf(a.y, bb.w, acc[1][3]);
        }
        __syncthreads();
    }

#pragma unroll
    for (int i = 0; i < 2; i++) {
        int gn = bnr + tr * 2 + i;
#pragma unroll
        for (int j = 0; j < 4; j++) {
            int gd = bd + tc * 4 + j;
            fbb[((long)b * Nn + gn) * Dd + gd] = acc[i][j] + Bf[(long)gn * Dd + gd];
        }
    }
}

// -------- gated moment reduction: out = fbb[j] + sum_i Acol[i]*fm*sigmoid(fm*s) ----
// block per (b,j), 256 threads, float2 per thread over d. f_m streamed exactly once.
__global__ void moment_kernel(const float* __restrict__ S,
                              const float* __restrict__ fbb,
                              const float* __restrict__ f_m,
                              const float* __restrict__ f_s,
                              float* __restrict__ out)
{
    int j = blockIdx.x, b = blockIdx.y;
    int t = threadIdx.x;              // 0..255 -> d = 2t, 2t+1
    __shared__ float Acol[Nn];        // A_b[b, i, j] over i
    if (t < Nn) Acol[t] = S[(long)(b * Nn + t) * Nn + j];
    __syncthreads();

    float2 s = *(const float2*)(f_s + (long)b * Dd + 2 * t);
    float hsx = 0.5f * s.x, hsy = 0.5f * s.y;
    const float2* fm = (const float2*)(f_m + ((long)(b * Nn) * Nn + j) * Dd) + t;
    const long istep = (long)Nn * Dd / 2;   // float2 stride per i

    float ax = 0.f, ay = 0.f;
#pragma unroll 8
    for (int i = 0; i < Nn; i++) {
        float2 x = fm[(long)i * istep];
        float a = Acol[i];
        float tx = tanh_approx(x.x * hsx);
        float ty = tanh_approx(x.y * hsy);
        ax = fmaf(a * x.x, fmaf(tx, 0.5f, 0.5f), ax);
        ay = fmaf(a * x.y, fmaf(ty, 0.5f, 0.5f), ay);
    }
    float2 r = *(const float2*)(fbb + (long)(b * Nn + j) * Dd + 2 * t);
    r.x += ax; r.y += ay;
    *(float2*)(out + (long)(b * Nn + j) * Dd + 2 * t) = r;
}

// ---------------- launch ----------------
extern "C" void kernel_launch(void* const* d_in, const int* in_sizes, int n_in,
                              void* d_out, int out_size)
{
    const float* f_b = (const float*)d_in[0];
    const float* f_w = (const float*)d_in[1];
    const float* f_s = (const float*)d_in[2];
    const float* f_m = (const float*)d_in[3];
    const float* Wq  = (const float*)d_in[4];
    const float* bq  = (const float*)d_in[5];
    const float* Wk  = (const float*)d_in[6];
    const float* bk  = (const float*)d_in[7];
    float* out = (float*)d_out;

    float* kk  = nullptr; cudaGetSymbolAddress((void**)&kk,  g_k);
    float* u   = nullptr; cudaGetSymbolAddress((void**)&u,   g_u);
    float* fbq = nullptr; cudaGetSymbolAddress((void**)&fbq, g_fbq);
    float* S   = nullptr; cudaGetSymbolAddress((void**)&S,   g_S);
    float* Sp  = nullptr; cudaGetSymbolAddress((void**)&Sp,  g_Sp);
    float* fbb = nullptr; cudaGetSymbolAddress((void**)&fbb, g_fbb);

    // 1) k = f_w @ Wk^T + bk   [80,512]
    {
        dim3 grid(Dd / 64, (Bb * Ll) / 16);
        gemm_nt16<<<grid, 256>>>(f_w, Wk, bk, kk);
    }
    // 2) u = k @ Wq            [80,512]   (logits = f_b.u + bq.k)
    {
        dim3 grid(Dd / 64, (Bb * Ll) / 16);
        gemm_nn16<<<grid, 256>>>(kk, Wq, u);
    }
    // 3) cross attention + gate -> f_bq
    {
        dim3 grid(Nn, Bb);
        cross_attn_kernel<<<grid, 640>>>(u, kk, bq, f_w, f_b, f_s, fbq);
    }
    // 4) S partials = split-K f_bq @ f_bq^T per batch
    {
        dim3 grid(Nn / 32, Nn / 32, Bb * KS);
        s_gemm_kernel<<<grid, 256>>>(fbq, Sp);
    }
    // 5) reduce partials + softmax -> A_b
    softmax_reduce_kernel<<<(Bb * Nn) / 4, 128>>>(Sp, S);
    // 6) fbb = A_b @ f_b + f_b
    {
        dim3 grid(Dd / 64, Nn / 32, Bb);
        fbb_gemm_kernel<<<grid, 256>>>(S, f_b, fbb);
    }
    // 7) moment: out = fbb + gated moment reduction
    {
        dim3 grid(Nn, Bb);
        moment_kernel<<<grid, 256>>>(S, fbb, f_m, f_s, out);
    }
    (void)in_sizes; (void)n_in; (void)out_size;
}

// round 6
// speedup vs baseline: 1.3324x; 1.0972x over previous
#include <cuda_runtime.h>
#include <math.h>

#define Bb 4
#define Nn 128
#define Ll 20
#define Dd 512
#define SCALE 0.044194173824159216f  // 1/sqrt(512)
#define KS 4                          // split-K factor for S GEMM
#define KCH (Dd / KS)                 // 128

// ---------------- scratch (no allocations allowed) ----------------
__device__ float g_k  [Bb*Ll*Dd];        // k = f_w Wk^T + bk        [80,512]
__device__ float g_u  [Bb*Ll*Dd];        // u = k Wq                 [80,512]
__device__ float g_fbq[Bb*Nn*Dd];        // gated boundary feats     [512,512]
__device__ float g_S  [Bb*Nn*Nn];        // A_b after softmax        [4,128,128]
__device__ float g_Sp [KS*Bb*Nn*Nn];     // split-K partials of S

__device__ __forceinline__ float tanh_approx(float x) {
    float y; asm("tanh.approx.f32 %0, %1;" : "=f"(y) : "f"(x)); return y;
}

// ======== 16-row NT GEMM with double-buffered smem: C[80,512] = A[80,512] B[512,512]^T (+bias)
__global__ void gemm_nt16(const float* __restrict__ A, const float* __restrict__ Bm,
                          const float* __restrict__ bias, float* __restrict__ C)
{
    const int K = Dd;
    int bm = blockIdx.y * 16;
    int bn = blockIdx.x * 64;

    __shared__ float Ast[2][32][18];
    __shared__ float Bst[2][32][68];

    int tid = threadIdx.x;
    int tr = tid >> 4, tc = tid & 15;
    int arow = tid >> 3;
    int acol = (tid & 7) * 4;
    int brow0 = tid >> 3;
    int brow1 = brow0 + 32;

    float4 av = make_float4(0.f,0.f,0.f,0.f), bv0, bv1;
    if (tid < 128) av = *(const float4*)(A + (long)(bm + arow) * K + acol);
    bv0 = *(const float4*)(Bm + (long)(bn + brow0) * K + acol);
    bv1 = *(const float4*)(Bm + (long)(bn + brow1) * K + acol);
    if (tid < 128) {
        Ast[0][acol+0][arow]=av.x; Ast[0][acol+1][arow]=av.y;
        Ast[0][acol+2][arow]=av.z; Ast[0][acol+3][arow]=av.w;
    }
    Bst[0][acol+0][brow0]=bv0.x; Bst[0][acol+1][brow0]=bv0.y;
    Bst[0][acol+2][brow0]=bv0.z; Bst[0][acol+3][brow0]=bv0.w;
    Bst[0][acol+0][brow1]=bv1.x; Bst[0][acol+1][brow1]=bv1.y;
    Bst[0][acol+2][brow1]=bv1.z; Bst[0][acol+3][brow1]=bv1.w;
    __syncthreads();

    float acc0=0.f, acc1=0.f, acc2=0.f, acc3=0.f;
    const int nit = K / 32;
    int buf = 0;
    for (int it = 0; it < nit; it++) {
        bool more = (it + 1 < nit);
        if (more) {
            int k0n = (it + 1) * 32;
            if (tid < 128) av = *(const float4*)(A + (long)(bm + arow) * K + k0n + acol);
            bv0 = *(const float4*)(Bm + (long)(bn + brow0) * K + k0n + acol);
            bv1 = *(const float4*)(Bm + (long)(bn + brow1) * K + k0n + acol);
        }
#pragma unroll
        for (int k = 0; k < 32; k++) {
            float a = Ast[buf][k][tr];
            float4 b = *(const float4*)&Bst[buf][k][tc * 4];
            acc0 = fmaf(a, b.x, acc0);
            acc1 = fmaf(a, b.y, acc1);
            acc2 = fmaf(a, b.z, acc2);
            acc3 = fmaf(a, b.w, acc3);
        }
        if (more) {
            int nb = buf ^ 1;
            if (tid < 128) {
                Ast[nb][acol+0][arow]=av.x; Ast[nb][acol+1][arow]=av.y;
                Ast[nb][acol+2][arow]=av.z; Ast[nb][acol+3][arow]=av.w;
            }
            Bst[nb][acol+0][brow0]=bv0.x; Bst[nb][acol+1][brow0]=bv0.y;
            Bst[nb][acol+2][brow0]=bv0.z; Bst[nb][acol+3][brow0]=bv0.w;
            Bst[nb][acol+0][brow1]=bv1.x; Bst[nb][acol+1][brow1]=bv1.y;
            Bst[nb][acol+2][brow1]=bv1.z; Bst[nb][acol+3][brow1]=bv1.w;
            __syncthreads();
            buf = nb;
        }
    }

    int gm = bm + tr;
    int gn = bn + tc * 4;
    float4 bb = bias ? *(const float4*)(bias + gn) : make_float4(0.f,0.f,0.f,0.f);
    C[(long)gm * Dd + gn + 0] = acc0 + bb.x;
    C[(long)gm * Dd + gn + 1] = acc1 + bb.y;
    C[(long)gm * Dd + gn + 2] = acc2 + bb.z;
    C[(long)gm * Dd + gn + 3] = acc3 + bb.w;
}

// ======== 16-row NN GEMM with double buffering: C[80,512] = A[80,512] B[512,512]
__global__ void gemm_nn16(const float* __restrict__ A, const float* __restrict__ Bm,
                          float* __restrict__ C)
{
    const int K = Dd;
    int bm = blockIdx.y * 16;
    int bn = blockIdx.x * 64;

    __shared__ float Ast[2][32][18];
    __shared__ float Bst[2][32][68];

    int tid = threadIdx.x;
    int tr = tid >> 4, tc = tid & 15;
    int arow = tid >> 3;
    int acol = (tid & 7) * 4;
    int bkr0 = tid >> 4;
    int bkr1 = bkr0 + 16;
    int bcol = (tid & 15) * 4;

    float4 av = make_float4(0.f,0.f,0.f,0.f), bv0, bv1;
    if (tid < 128) av = *(const float4*)(A + (long)(bm + arow) * K + acol);
    bv0 = *(const float4*)(Bm + (long)bkr0 * Dd + bn + bcol);
    bv1 = *(const float4*)(Bm + (long)bkr1 * Dd + bn + bcol);
    if (tid < 128) {
        Ast[0][acol+0][arow]=av.x; Ast[0][acol+1][arow]=av.y;
        Ast[0][acol+2][arow]=av.z; Ast[0][acol+3][arow]=av.w;
    }
    *(float4*)&Bst[0][bkr0][bcol] = bv0;
    *(float4*)&Bst[0][bkr1][bcol] = bv1;
    __syncthreads();

    float acc0=0.f, acc1=0.f, acc2=0.f, acc3=0.f;
    const int nit = K / 32;
    int buf = 0;
    for (int it = 0; it < nit; it++) {
        bool more = (it + 1 < nit);
        if (more) {
            int k0n = (it + 1) * 32;
            if (tid < 128) av = *(const float4*)(A + (long)(bm + arow) * K + k0n + acol);
            bv0 = *(const float4*)(Bm + (long)(k0n + bkr0) * Dd + bn + bcol);
            bv1 = *(const float4*)(Bm + (long)(k0n + bkr1) * Dd + bn + bcol);
        }
#pragma unroll
        for (int k = 0; k < 32; k++) {
            float a = Ast[buf][k][tr];
            float4 b = *(const float4*)&Bst[buf][k][tc * 4];
            acc0 = fmaf(a, b.x, acc0);
            acc1 = fmaf(a, b.y, acc1);
            acc2 = fmaf(a, b.z, acc2);
            acc3 = fmaf(a, b.w, acc3);
        }
        if (more) {
            int nb = buf ^ 1;
            if (tid < 128) {
                Ast[nb][acol+0][arow]=av.x; Ast[nb][acol+1][arow]=av.y;
                Ast[nb][acol+2][arow]=av.z; Ast[nb][acol+3][arow]=av.w;
            }
            *(float4*)&Bst[nb][bkr0][bcol] = bv0;
            *(float4*)&Bst[nb][bkr1][bcol] = bv1;
            __syncthreads();
            buf = nb;
        }
    }

    int gm = bm + tr;
    int gn = bn + tc * 4;
    C[(long)gm * Dd + gn + 0] = acc0;
    C[(long)gm * Dd + gn + 1] = acc1;
    C[(long)gm * Dd + gn + 2] = acc2;
    C[(long)gm * Dd + gn + 3] = acc3;
}

// ------- cross attention v2: 8 boundary rows per block, tiles in dynamic smem ----
// logit[b,n,l] = f_b[b,n].u[b,l] + bq.k[b,l]
// grid (Nn/8, Bb), 512 threads. smem: u(40K) + f_w(40K) + f_b8(16K) + small.
#define CROSS_SMEM ((2*Ll*Dd + 8*Dd + 32 + 160 + 160) * (int)sizeof(float))
__global__ void cross_attn8(const float* __restrict__ u,
                            const float* __restrict__ k,
                            const float* __restrict__ bq,
                            const float* __restrict__ f_w,
                            const float* __restrict__ f_b,
                            const float* __restrict__ f_s,
                            float* __restrict__ fbq)
{
    extern __shared__ float sm[];
    float* uw  = sm;                       // [Ll][Dd]
    float* fw  = sm + Ll * Dd;             // [Ll][Dd]
    float* fbs = fw + Ll * Dd;             // [8][Dd]
    float* cv  = fbs + 8 * Dd;             // [Ll] (+pad to 32)
    float* lg  = cv + 32;                  // [160] logits (l*8+n)
    float* wt  = lg + 160;                 // [160] weights

    int b  = blockIdx.y;
    int n0 = blockIdx.x * 8;
    int t  = threadIdx.x;                  // 512
    int w = t >> 5, lane = t & 31;

    // load u[b], f_w[b] (2560 float4 each), f_b rows (1024 float4)
    const float4* us  = (const float4*)(u   + (long)b * Ll * Dd);
    const float4* fws = (const float4*)(f_w + (long)b * Ll * Dd);
    for (int i = t; i < (Ll * Dd) / 4; i += 512) {
        ((float4*)uw)[i] = us[i];
        ((float4*)fw)[i] = fws[i];
    }
    const float4* fbsrc = (const float4*)(f_b + (long)(b * Nn + n0) * Dd);
    for (int i = t; i < (8 * Dd) / 4; i += 512) ((float4*)fbs)[i] = fbsrc[i];

    // cv[l] = bq . k[b,l]
    for (int l = w; l < Ll; l += 16) {
        const float* kr = k + (long)(b * Ll + l) * Dd;
        float p = 0.f;
#pragma unroll
        for (int dd = 0; dd < Dd / 32; dd++)
            p = fmaf(bq[lane + dd * 32], kr[lane + dd * 32], p);
#pragma unroll
        for (int off = 16; off > 0; off >>= 1) p += __shfl_xor_sync(0xffffffff, p, off);
        if (lane == 0) cv[l] = p;
    }
    __syncthreads();

    // logits: 160 dots (n,l), warp per dot
    for (int idx = w; idx < 8 * Ll; idx += 16) {
        int n = idx & 7, l = idx >> 3;
        const float* fr = fbs + n * Dd;
        const float* ur = uw + l * Dd;
        float p = 0.f;
#pragma unroll
        for (int dd = 0; dd < Dd / 32; dd++)
            p = fmaf(fr[lane + dd * 32], ur[lane + dd * 32], p);
#pragma unroll
        for (int off = 16; off > 0; off >>= 1) p += __shfl_xor_sync(0xffffffff, p, off);
        if (lane == 0) lg[l * 8 + n] = (p + cv[l]) * SCALE;
    }
    __syncthreads();

    // per-n softmax over Ll (threads 0..7)
    if (t < 8) {
        float mx = -1e30f;
#pragma unroll
        for (int l = 0; l < Ll; l++) mx = fmaxf(mx, lg[l * 8 + t]);
        float sum = 0.f;
#pragma unroll
        for (int l = 0; l < Ll; l++) { float e = __expf(lg[l * 8 + t] - mx); wt[l * 8 + t] = e; sum += e; }
        float inv = __fdividef(1.f, sum);
#pragma unroll
        for (int l = 0; l < Ll; l++) wt[l * 8 + t] *= inv;
    }
    __syncthreads();

    // output: per thread d = t, all 8 n
    float fsv = f_s[(long)b * Dd + t];
#pragma unroll
    for (int n = 0; n < 8; n++) {
        float acc = 0.f;
#pragma unroll
        for (int l = 0; l < Ll; l++) acc = fmaf(wt[l * 8 + n], fw[l * Dd + t], acc);
        float v = fbs[n * Dd + t] * (acc + fsv);
        fbq[(long)(b * Nn + n0 + n) * Dd + t] = v;
    }
}

// -------- S split-K GEMM, single-sync: load full 32x128 K-chunks into smem ----
__global__ void s_gemm_kernel(const float* __restrict__ fbq, float* __restrict__ Sp)
{
    int b = blockIdx.z / KS;
    int s = blockIdx.z % KS;
    const float* A = fbq + (long)b * Nn * Dd;
    int bm = blockIdx.y * 32;
    int bn = blockIdx.x * 32;
    int kbase = s * KCH;

    __shared__ float As[KCH][34];
    __shared__ float Bs[KCH][34];

    int tid = threadIdx.x;
    int arow = tid >> 3;
    int ac   = (tid & 7) * 4;

#pragma unroll
    for (int q = 0; q < 4; q++) {
        int col = ac + q * 32;
        float4 av = *(const float4*)(A + (long)(bm + arow) * Dd + kbase + col);
        As[col+0][arow]=av.x; As[col+1][arow]=av.y; As[col+2][arow]=av.z; As[col+3][arow]=av.w;
        float4 bv = *(const float4*)(A + (long)(bn + arow) * Dd + kbase + col);
        Bs[col+0][arow]=bv.x; Bs[col+1][arow]=bv.y; Bs[col+2][arow]=bv.z; Bs[col+3][arow]=bv.w;
    }
    __syncthreads();

    int tr = tid >> 4, tc = tid & 15;
    float a00=0.f, a01=0.f, a10=0.f, a11=0.f;
#pragma unroll 8
    for (int k = 0; k < KCH; k++) {
        float2 a  = *(const float2*)&As[k][tr * 2];
        float2 bb = *(const float2*)&Bs[k][tc * 2];
        a00 = fmaf(a.x, bb.x, a00);
        a01 = fmaf(a.x, bb.y, a01);
        a10 = fmaf(a.y, bb.x, a10);
        a11 = fmaf(a.y, bb.y, a11);
    }

    float* o = Sp + ((long)(s * Bb + b) * Nn) * Nn;
    int gm = bm + tr * 2, gn = bn + tc * 2;
    o[(long)gm * Nn + gn]           = a00;
    o[(long)gm * Nn + gn + 1]       = a01;
    o[(long)(gm + 1) * Nn + gn]     = a10;
    o[(long)(gm + 1) * Nn + gn + 1] = a11;
}

// -------- fused: reduce split-K + row softmax + fbb GEMM ----------------
// grid (Dd/64, Nn/32, Bb), 256 threads.
// Writes A_b to S (only x==0 blocks) and out = A_b @ f_b + f_b.
__global__ void softmax_fbb_kernel(const float* __restrict__ Sp, const float* __restrict__ f_b,
                                   float* __restrict__ S, float* __restrict__ out)
{
    int b  = blockIdx.z;
    int rt = blockIdx.y * 32;
    int dt = blockIdx.x * 64;

    __shared__ float As[Nn][34];    // [m][row]: A_b^T tile (rows rt..rt+31, all 128 cols)
    __shared__ float Bst[32][68];

    int tid = threadIdx.x;

    // phase 1: reduce split-K partials into As (scaled logits)
    {
        int r  = tid >> 3;             // 0..31
        int c0 = (tid & 7) * 16;
#pragma unroll
        for (int cc = 0; cc < 16; cc += 4) {
            float4 acc4 = make_float4(0.f, 0.f, 0.f, 0.f);
#pragma unroll
            for (int s = 0; s < KS; s++) {
                float4 v = *(const float4*)(Sp + ((long)(s * Bb + b) * Nn + rt + r) * Nn + c0 + cc);
                acc4.x += v.x; acc4.y += v.y; acc4.z += v.z; acc4.w += v.w;
            }
            As[c0+cc+0][r] = acc4.x * SCALE;
            As[c0+cc+1][r] = acc4.y * SCALE;
            As[c0+cc+2][r] = acc4.z * SCALE;
            As[c0+cc+3][r] = acc4.w * SCALE;
        }
    }
    __syncthreads();

    // phase 2: row softmax (8 warps, 4 rows each)
    {
        int w = tid >> 5, lane = tid & 31;
#pragma unroll
        for (int rr = w * 4; rr < w * 4 + 4; rr++) {
            float v[4];
#pragma unroll
            for (int j = 0; j < 4; j++) v[j] = As[lane + 32 * j][rr];
            float mx = fmaxf(fmaxf(v[0], v[1]), fmaxf(v[2], v[3]));
#pragma unroll
            for (int off = 16; off > 0; off >>= 1) mx = fmaxf(mx, __shfl_xor_sync(0xffffffff, mx, off));
            float sum = 0.f;
#pragma unroll
            for (int j = 0; j < 4; j++) { v[j] = __expf(v[j] - mx); sum += v[j]; }
#pragma unroll
            for (int off = 16; off > 0; off >>= 1) sum += __shfl_xor_sync(0xffffffff, sum, off);
            float inv = __fdividef(1.f, sum);
#pragma unroll
            for (int j = 0; j < 4; j++) {
                float a = v[j] * inv;
                As[lane + 32 * j][rr] = a;
                if (blockIdx.x == 0) S[((long)(b * Nn) + rt + rr) * Nn + lane + 32 * j] = a;
            }
        }
    }
    __syncthreads();

    // phase 3: out[rows, dtile] = A_b[rows,:] @ f_b[b][:, dtile] + f_b[rows, dtile]
    const float* Bf = f_b + (long)b * Nn * Dd;
    int tr = tid >> 4, tc = tid & 15;
    int bkr0 = tid >> 4, bkr1 = bkr0 + 16;
    int bcol = (tid & 15) * 4;

    float acc[2][4];
#pragma unroll
    for (int i = 0; i < 2; i++)
#pragma unroll
        for (int j = 0; j < 4; j++) acc[i][j] = 0.f;

    for (int m0 = 0; m0 < Nn; m0 += 32) {
        *(float4*)&Bst[bkr0][bcol] = *(const float4*)(Bf + (long)(m0 + bkr0) * Dd + dt + bcol);
        *(float4*)&Bst[bkr1][bcol] = *(const float4*)(Bf + (long)(m0 + bkr1) * Dd + dt + bcol);
        __syncthreads();
#pragma unroll
        for (int k = 0; k < 32; k++) {
            float2 a = *(const float2*)&As[m0 + k][tr * 2];
            float4 bb = *(const float4*)&Bst[k][tc * 4];
            acc[0][0] = fmaf(a.x, bb.x, acc[0][0]);
            acc[0][1] = fmaf(a.x, bb.y, acc[0][1]);
            acc[0][2] = fmaf(a.x, bb.z, acc[0][2]);
            acc[0][3] = fmaf(a.x, bb.w, acc[0][3]);
            acc[1][0] = fmaf(a.y, bb.x, acc[1][0]);
            acc[1][1] = fmaf(a.y, bb.y, acc[1][1]);
            acc[1][2] = fmaf(a.y, bb.z, acc[1][2]);
            acc[1][3] = fmaf(a.y, bb.w, acc[1][3]);
        }
        __syncthreads();
    }

#pragma unroll
    for (int i = 0; i < 2; i++) {
        int gn = rt + tr * 2 + i;
#pragma unroll
        for (int j = 0; j < 4; j++) {
            int gd = dt + tc * 4 + j;
            out[((long)b * Nn + gn) * Dd + gd] = acc[i][j] + Bf[(long)gn * Dd + gd];
        }
    }
}

// -------- gated moment reduction: out += sum_i Acol[i]*fm*sigmoid(fm*s) ----
// block per (b,j), 128 threads, float4 per thread over d. f_m streamed once (ldcs).
__global__ void moment_kernel(const float* __restrict__ S,
                              const float* __restrict__ f_m,
                              const float* __restrict__ f_s,
                              float* __restrict__ out)
{
    int j = blockIdx.x, b = blockIdx.y;
    int t = threadIdx.x;                  // 0..127 -> d = 4t..4t+3
    __shared__ float Acol[Nn];            // A_b[b, i, j] over i
    Acol[t] = S[(long)(b * Nn + t) * Nn + j];
    __syncthreads();

    float4 s = *(const float4*)(f_s + (long)b * Dd + 4 * t);
    float hx = 0.5f * s.x, hy = 0.5f * s.y, hz = 0.5f * s.z, hw = 0.5f * s.w;
    const float4* fm = (const float4*)(f_m + ((long)(b * Nn) * Nn + j) * Dd) + t;
    const long istep = (long)Nn * Dd / 4;

    float ax = 0.f, ay = 0.f, az = 0.f, aw = 0.f;
#pragma unroll 8
    for (int i = 0; i < Nn; i++) {
        float4 x = __ldcs(&fm[(long)i * istep]);
        float a = Acol[i];
        ax = fmaf(a * x.x, fmaf(tanh_approx(x.x * hx), 0.5f, 0.5f), ax);
        ay = fmaf(a * x.y, fmaf(tanh_approx(x.y * hy), 0.5f, 0.5f), ay);
        az = fmaf(a * x.z, fmaf(tanh_approx(x.z * hz), 0.5f, 0.5f), az);
        aw = fmaf(a * x.w, fmaf(tanh_approx(x.w * hw), 0.5f, 0.5f), aw);
    }
    float4* op = (float4*)(out + (long)(b * Nn + j) * Dd) + t;
    float4 r = *op;
    r.x += ax; r.y += ay; r.z += az; r.w += aw;
    *op = r;
}

// ---------------- launch ----------------
extern "C" void kernel_launch(void* const* d_in, const int* in_sizes, int n_in,
                              void* d_out, int out_size)
{
    const float* f_b = (const float*)d_in[0];
    const float* f_w = (const float*)d_in[1];
    const float* f_s = (const float*)d_in[2];
    const float* f_m = (const float*)d_in[3];
    const float* Wq  = (const float*)d_in[4];
    const float* bq  = (const float*)d_in[5];
    const float* Wk  = (const float*)d_in[6];
    const float* bk  = (const float*)d_in[7];
    float* out = (float*)d_out;

    float* kk  = nullptr; cudaGetSymbolAddress((void**)&kk,  g_k);
    float* u   = nullptr; cudaGetSymbolAddress((void**)&u,   g_u);
    float* fbq = nullptr; cudaGetSymbolAddress((void**)&fbq, g_fbq);
    float* S   = nullptr; cudaGetSymbolAddress((void**)&S,   g_S);
    float* Sp  = nullptr; cudaGetSymbolAddress((void**)&Sp,  g_Sp);

    cudaFuncSetAttribute(cross_attn8, cudaFuncAttributeMaxDynamicSharedMemorySize, CROSS_SMEM);

    // 1) k = f_w @ Wk^T + bk   [80,512]
    {
        dim3 grid(Dd / 64, (Bb * Ll) / 16);
        gemm_nt16<<<grid, 256>>>(f_w, Wk, bk, kk);
    }
    // 2) u = k @ Wq            [80,512]   (logits = f_b.u + bq.k)
    {
        dim3 grid(Dd / 64, (Bb * Ll) / 16);
        gemm_nn16<<<grid, 256>>>(kk, Wq, u);
    }
    // 3) cross attention + gate -> f_bq (8 rows per block)
    {
        dim3 grid(Nn / 8, Bb);
        cross_attn8<<<grid, 512, CROSS_SMEM>>>(u, kk, bq, f_w, f_b, f_s, fbq);
    }
    // 4) S partials = split-K f_bq @ f_bq^T per batch
    {
        dim3 grid(Nn / 32, Nn / 32, Bb * KS);
        s_gemm_kernel<<<grid, 256>>>(fbq, Sp);
    }
    // 5) fused reduce + softmax + fbb: writes S and out = A_b@f_b + f_b
    {
        dim3 grid(Dd / 64, Nn / 32, Bb);
        softmax_fbb_kernel<<<grid, 256>>>(Sp, f_b, S, out);
    }
    // 6) moment: out += gated moment reduction
    {
        dim3 grid(Nn, Bb);
        moment_kernel<<<grid, 128>>>(S, f_m, f_s, out);
    }
    (void)in_sizes; (void)n_in; (void)out_size;
}

// round 8
// speedup vs baseline: 1.5364x; 1.1531x over previous
#include <cuda_runtime.h>
#include <math.h>

#define Bb 4
#define Nn 128
#define Ll 20
#define Dd 512
#define SCALE 0.044194173824159216f  // 1/sqrt(512)
#define KS 8                          // split-K factor for S GEMM
#define KCH (Dd / KS)                 // 64

// ---------------- scratch (no allocations allowed) ----------------
__device__ float g_k  [Bb*Ll*Dd];        // k = f_w Wk^T + bk        [80,512]
__device__ float g_u  [Bb*Ll*Dd];        // u = k Wq                 [80,512]
__device__ float g_fbq[Bb*Nn*Dd];        // gated boundary feats     [512,512]
__device__ float g_S  [Bb*Nn*Nn];        // A_b after softmax        [4,128,128]
__device__ float g_Sp [KS*Bb*Nn*Nn];     // split-K partials of S

__device__ __forceinline__ float tanh_approx(float x) {
    float y; asm("tanh.approx.f32 %0, %1;" : "=f"(y) : "f"(x)); return y;
}

// ======== NT GEMM, BM=16 BN=32, 128 threads, double-buffered ========
// C[80,512] = A[80,512] @ B[512,512]^T (+bias). grid (Dd/32=16, 80/16=5).
__global__ void gemm_nt32(const float* __restrict__ A, const float* __restrict__ Bm,
                          const float* __restrict__ bias, float* __restrict__ C)
{
    const int K = Dd;
    int bm = blockIdx.y * 16;
    int bn = blockIdx.x * 32;

    __shared__ float Ast[2][32][18];
    __shared__ float Bst[2][32][36];

    int tid = threadIdx.x;            // 128
    int r  = tid >> 3;                // 0..15 (output row, also A row)
    int c4 = (tid & 7) * 4;           // 0..28 (output col group, also k col group)
    int brow0 = tid >> 3;             // 0..15
    int brow1 = brow0 + 16;

    float4 av, bv0, bv1;
    av  = *(const float4*)(A  + (long)(bm + r) * K + c4);
    bv0 = *(const float4*)(Bm + (long)(bn + brow0) * K + c4);
    bv1 = *(const float4*)(Bm + (long)(bn + brow1) * K + c4);
    Ast[0][c4+0][r]=av.x; Ast[0][c4+1][r]=av.y; Ast[0][c4+2][r]=av.z; Ast[0][c4+3][r]=av.w;
    Bst[0][c4+0][brow0]=bv0.x; Bst[0][c4+1][brow0]=bv0.y;
    Bst[0][c4+2][brow0]=bv0.z; Bst[0][c4+3][brow0]=bv0.w;
    Bst[0][c4+0][brow1]=bv1.x; Bst[0][c4+1][brow1]=bv1.y;
    Bst[0][c4+2][brow1]=bv1.z; Bst[0][c4+3][brow1]=bv1.w;
    __syncthreads();

    float a0=0.f, a1=0.f, a2=0.f, a3=0.f;
    const int nit = K / 32;
    int buf = 0;
    for (int it = 0; it < nit; it++) {
        bool more = (it + 1 < nit);
        if (more) {
            int k0n = (it + 1) * 32;
            av  = *(const float4*)(A  + (long)(bm + r) * K + k0n + c4);
            bv0 = *(const float4*)(Bm + (long)(bn + brow0) * K + k0n + c4);
            bv1 = *(const float4*)(Bm + (long)(bn + brow1) * K + k0n + c4);
        }
#pragma unroll
        for (int k = 0; k < 32; k++) {
            float a = Ast[buf][k][r];
            float4 b = *(const float4*)&Bst[buf][k][c4];
            a0 = fmaf(a, b.x, a0);
            a1 = fmaf(a, b.y, a1);
            a2 = fmaf(a, b.z, a2);
            a3 = fmaf(a, b.w, a3);
        }
        if (more) {
            int nb = buf ^ 1;
            Ast[nb][c4+0][r]=av.x; Ast[nb][c4+1][r]=av.y;
            Ast[nb][c4+2][r]=av.z; Ast[nb][c4+3][r]=av.w;
            Bst[nb][c4+0][brow0]=bv0.x; Bst[nb][c4+1][brow0]=bv0.y;
            Bst[nb][c4+2][brow0]=bv0.z; Bst[nb][c4+3][brow0]=bv0.w;
            Bst[nb][c4+0][brow1]=bv1.x; Bst[nb][c4+1][brow1]=bv1.y;
            Bst[nb][c4+2][brow1]=bv1.z; Bst[nb][c4+3][brow1]=bv1.w;
            __syncthreads();
            buf = nb;
        }
    }

    int gm = bm + r, gn = bn + c4;
    float4 bb = bias ? *(const float4*)(bias + gn) : make_float4(0.f,0.f,0.f,0.f);
    C[(long)gm * Dd + gn + 0] = a0 + bb.x;
    C[(long)gm * Dd + gn + 1] = a1 + bb.y;
    C[(long)gm * Dd + gn + 2] = a2 + bb.z;
    C[(long)gm * Dd + gn + 3] = a3 + bb.w;
}

// ======== NN GEMM, BM=16 BN=32, 128 threads, double-buffered ========
// C[80,512] = A[80,512] @ B[512,512]. grid (16, 5).
__global__ void gemm_nn32(const float* __restrict__ A, const float* __restrict__ Bm,
                          float* __restrict__ C)
{
    const int K = Dd;
    int bm = blockIdx.y * 16;
    int bn = blockIdx.x * 32;

    __shared__ float Ast[2][32][18];
    __shared__ float Bst[2][32][36];

    int tid = threadIdx.x;
    int r  = tid >> 3;
    int c4 = (tid & 7) * 4;
    int bkr0 = tid >> 3;              // 0..15
    int bkr1 = bkr0 + 16;

    float4 av, bv0, bv1;
    av  = *(const float4*)(A + (long)(bm + r) * K + c4);
    bv0 = *(const float4*)(Bm + (long)bkr0 * Dd + bn + c4);
    bv1 = *(const float4*)(Bm + (long)bkr1 * Dd + bn + c4);
    Ast[0][c4+0][r]=av.x; Ast[0][c4+1][r]=av.y; Ast[0][c4+2][r]=av.z; Ast[0][c4+3][r]=av.w;
    *(float4*)&Bst[0][bkr0][c4] = bv0;
    *(float4*)&Bst[0][bkr1][c4] = bv1;
    __syncthreads();

    float a0=0.f, a1=0.f, a2=0.f, a3=0.f;
    const int nit = K / 32;
    int buf = 0;
    for (int it = 0; it < nit; it++) {
        bool more = (it + 1 < nit);
        if (more) {
            int k0n = (it + 1) * 32;
            av  = *(const float4*)(A + (long)(bm + r) * K + k0n + c4);
            bv0 = *(const float4*)(Bm + (long)(k0n + bkr0) * Dd + bn + c4);
            bv1 = *(const float4*)(Bm + (long)(k0n + bkr1) * Dd + bn + c4);
        }
#pragma unroll
        for (int k = 0; k < 32; k++) {
            float a = Ast[buf][k][r];
            float4 b = *(const float4*)&Bst[buf][k][c4];
            a0 = fmaf(a, b.x, a0);
            a1 = fmaf(a, b.y, a1);
            a2 = fmaf(a, b.z, a2);
            a3 = fmaf(a, b.w, a3);
        }
        if (more) {
            int nb = buf ^ 1;
            Ast[nb][c4+0][r]=av.x; Ast[nb][c4+1][r]=av.y;
            Ast[nb][c4+2][r]=av.z; Ast[nb][c4+3][r]=av.w;
            *(float4*)&Bst[nb][bkr0][c4] = bv0;
            *(float4*)&Bst[nb][bkr1][c4] = bv1;
            __syncthreads();
            buf = nb;
        }
    }

    int gm = bm + r, gn = bn + c4;
    C[(long)gm * Dd + gn + 0] = a0;
    C[(long)gm * Dd + gn + 1] = a1;
    C[(long)gm * Dd + gn + 2] = a2;
    C[(long)gm * Dd + gn + 3] = a3;
}

// ------- cross attention: 8 boundary rows per block, tiles in dynamic smem ----
#define CROSS_SMEM ((2*Ll*Dd + 8*Dd + 32 + 160 + 160) * (int)sizeof(float))
__global__ void cross_attn8(const float* __restrict__ u,
                            const float* __restrict__ k,
                            const float* __restrict__ bq,
                            const float* __restrict__ f_w,
                            const float* __restrict__ f_b,
                            const float* __restrict__ f_s,
                            float* __restrict__ fbq)
{
    extern __shared__ float sm[];
    float* uw  = sm;                       // [Ll][Dd]
    float* fw  = sm + Ll * Dd;             // [Ll][Dd]
    float* fbs = fw + Ll * Dd;             // [8][Dd]
    float* cv  = fbs + 8 * Dd;             // [Ll] (+pad)
    float* lg  = cv + 32;                  // [160]
    float* wt  = lg + 160;                 // [160]

    int b  = blockIdx.y;
    int n0 = blockIdx.x * 8;
    int t  = threadIdx.x;                  // 512
    int w = t >> 5, lane = t & 31;

    const float4* us  = (const float4*)(u   + (long)b * Ll * Dd);
    const float4* fws = (const float4*)(f_w + (long)b * Ll * Dd);
    for (int i = t; i < (Ll * Dd) / 4; i += 512) {
        ((float4*)uw)[i] = us[i];
        ((float4*)fw)[i] = fws[i];
    }
    const float4* fbsrc = (const float4*)(f_b + (long)(b * Nn + n0) * Dd);
    for (int i = t; i < (8 * Dd) / 4; i += 512) ((float4*)fbs)[i] = fbsrc[i];

    for (int l = w; l < Ll; l += 16) {
        const float* kr = k + (long)(b * Ll + l) * Dd;
        float p = 0.f;
#pragma unroll
        for (int dd = 0; dd < Dd / 32; dd++)
            p = fmaf(bq[lane + dd * 32], kr[lane + dd * 32], p);
#pragma unroll
        for (int off = 16; off > 0; off >>= 1) p += __shfl_xor_sync(0xffffffff, p, off);
        if (lane == 0) cv[l] = p;
    }
    __syncthreads();

    for (int idx = w; idx < 8 * Ll; idx += 16) {
        int n = idx & 7, l = idx >> 3;
        const float* fr = fbs + n * Dd;
        const float* ur = uw + l * Dd;
        float p = 0.f;
#pragma unroll
        for (int dd = 0; dd < Dd / 32; dd++)
            p = fmaf(fr[lane + dd * 32], ur[lane + dd * 32], p);
#pragma unroll
        for (int off = 16; off > 0; off >>= 1) p += __shfl_xor_sync(0xffffffff, p, off);
        if (lane == 0) lg[l * 8 + n] = (p + cv[l]) * SCALE;
    }
    __syncthreads();

    if (t < 8) {
        float mx = -1e30f;
#pragma unroll
        for (int l = 0; l < Ll; l++) mx = fmaxf(mx, lg[l * 8 + t]);
        float sum = 0.f;
#pragma unroll
        for (int l = 0; l < Ll; l++) { float e = __expf(lg[l * 8 + t] - mx); wt[l * 8 + t] = e; sum += e; }
        float inv = __fdividef(1.f, sum);
#pragma unroll
        for (int l = 0; l < Ll; l++) wt[l * 8 + t] *= inv;
    }
    __syncthreads();

    float fsv = f_s[(long)b * Dd + t];
#pragma unroll
    for (int n = 0; n < 8; n++) {
        float acc = 0.f;
#pragma unroll
        for (int l = 0; l < Ll; l++) acc = fmaf(wt[l * 8 + n], fw[l * Dd + t], acc);
        float v = fbs[n * Dd + t] * (acc + fsv);
        fbq[(long)(b * Nn + n0 + n) * Dd + t] = v;
    }
}

// -------- S split-K GEMM (KS=8, KCH=64), single-sync ----------------
// grid (4, 4, Bb*KS = 32) -> 512 blocks, 256 threads, 2x2 per thread.
__global__ void s_gemm_kernel(const float* __restrict__ fbq, float* __restrict__ Sp)
{
    int b = blockIdx.z / KS;
    int s = blockIdx.z % KS;
    const float* A = fbq + (long)b * Nn * Dd;
    int bm = blockIdx.y * 32;
    int bn = blockIdx.x * 32;
    int kbase = s * KCH;

    __shared__ float As[KCH][34];   // even stride -> float2 aligned
    __shared__ float Bs[KCH][34];

    int tid = threadIdx.x;
    int arow = tid >> 3;            // 0..31
    int ac   = (tid & 7) * 4;       // 0..28

#pragma unroll
    for (int q = 0; q < 2; q++) {
        int col = ac + q * 32;
        float4 av = *(const float4*)(A + (long)(bm + arow) * Dd + kbase + col);
        As[col+0][arow]=av.x; As[col+1][arow]=av.y; As[col+2][arow]=av.z; As[col+3][arow]=av.w;
        float4 bv = *(const float4*)(A + (long)(bn + arow) * Dd + kbase + col);
        Bs[col+0][arow]=bv.x; Bs[col+1][arow]=bv.y; Bs[col+2][arow]=bv.z; Bs[col+3][arow]=bv.w;
    }
    __syncthreads();

    int tr = tid >> 4, tc = tid & 15;
    float a00=0.f, a01=0.f, a10=0.f, a11=0.f;
#pragma unroll 8
    for (int k = 0; k < KCH; k++) {
        float2 a  = *(const float2*)&As[k][tr * 2];
        float2 bb = *(const float2*)&Bs[k][tc * 2];
        a00 = fmaf(a.x, bb.x, a00);
        a01 = fmaf(a.x, bb.y, a01);
        a10 = fmaf(a.y, bb.x, a10);
        a11 = fmaf(a.y, bb.y, a11);
    }

    float* o = Sp + ((long)(s * Bb + b) * Nn) * Nn;
    int gm = bm + tr * 2, gn = bn + tc * 2;
    o[(long)gm * Nn + gn]           = a00;
    o[(long)gm * Nn + gn + 1]       = a01;
    o[(long)(gm + 1) * Nn + gn]     = a10;
    o[(long)(gm + 1) * Nn + gn + 1] = a11;
}

// -------- fused: reduce split-K + row softmax + fbb GEMM ----------------
__global__ void softmax_fbb_kernel(const float* __restrict__ Sp, const float* __restrict__ f_b,
                                   float* __restrict__ S, float* __restrict__ out)
{
    int b  = blockIdx.z;
    int rt = blockIdx.y * 32;
    int dt = blockIdx.x * 64;

    __shared__ float As[Nn][34];
    __shared__ float Bst[32][68];

    int tid = threadIdx.x;

    // phase 1: reduce split-K partials (scaled logits)
    {
        int r  = tid >> 3;
        int c0 = (tid & 7) * 16;
#pragma unroll
        for (int cc = 0; cc < 16; cc += 4) {
            float4 acc4 = make_float4(0.f, 0.f, 0.f, 0.f);
#pragma unroll
            for (int s = 0; s < KS; s++) {
                float4 v = *(const float4*)(Sp + ((long)(s * Bb + b) * Nn + rt + r) * Nn + c0 + cc);
                acc4.x += v.x; acc4.y += v.y; acc4.z += v.z; acc4.w += v.w;
            }
            As[c0+cc+0][r] = acc4.x * SCALE;
            As[c0+cc+1][r] = acc4.y * SCALE;
            As[c0+cc+2][r] = acc4.z * SCALE;
            As[c0+cc+3][r] = acc4.w * SCALE;
        }
    }
    __syncthreads();

    // phase 2: row softmax
    {
        int w = tid >> 5, lane = tid & 31;
#pragma unroll
        for (int rr = w * 4; rr < w * 4 + 4; rr++) {
            float v[4];
#pragma unroll
            for (int j = 0; j < 4; j++) v[j] = As[lane + 32 * j][rr];
            float mx = fmaxf(fmaxf(v[0], v[1]), fmaxf(v[2], v[3]));
#pragma unroll
            for (int off = 16; off > 0; off >>= 1) mx = fmaxf(mx, __shfl_xor_sync(0xffffffff, mx, off));
            float sum = 0.f;
#pragma unroll
            for (int j = 0; j < 4; j++) { v[j] = __expf(v[j] - mx); sum += v[j]; }
#pragma unroll
            for (int off = 16; off > 0; off >>= 1) sum += __shfl_xor_sync(0xffffffff, sum, off);
            float inv = __fdividef(1.f, sum);
#pragma unroll
            for (int j = 0; j < 4; j++) {
                float a = v[j] * inv;
                As[lane + 32 * j][rr] = a;
                if (blockIdx.x == 0) S[((long)(b * Nn) + rt + rr) * Nn + lane + 32 * j] = a;
            }
        }
    }
    __syncthreads();

    // phase 3: out = A_b @ f_b + f_b for this tile
    const float* Bf = f_b + (long)b * Nn * Dd;
    int tr = tid >> 4, tc = tid & 15;
    int bkr0 = tid >> 4, bkr1 = bkr0 + 16;
    int bcol = (tid & 15) * 4;

    float acc[2][4];
#pragma unroll
    for (int i = 0; i < 2; i++)
#pragma unroll
        for (int j = 0; j < 4; j++) acc[i][j] = 0.f;

    for (int m0 = 0; m0 < Nn; m0 += 32) {
        *(float4*)&Bst[bkr0][bcol] = *(const float4*)(Bf + (long)(m0 + bkr0) * Dd + dt + bcol);
        *(float4*)&Bst[bkr1][bcol] = *(const float4*)(Bf + (long)(m0 + bkr1) * Dd + dt + bcol);
        __syncthreads();
#pragma unroll
        for (int k = 0; k < 32; k++) {
            float2 a = *(const float2*)&As[m0 + k][tr * 2];
            float4 bb = *(const float4*)&Bst[k][tc * 4];
            acc[0][0] = fmaf(a.x, bb.x, acc[0][0]);
            acc[0][1] = fmaf(a.x, bb.y, acc[0][1]);
            acc[0][2] = fmaf(a.x, bb.z, acc[0][2]);
            acc[0][3] = fmaf(a.x, bb.w, acc[0][3]);
            acc[1][0] = fmaf(a.y, bb.x, acc[1][0]);
            acc[1][1] = fmaf(a.y, bb.y, acc[1][1]);
            acc[1][2] = fmaf(a.y, bb.z, acc[1][2]);
            acc[1][3] = fmaf(a.y, bb.w, acc[1][3]);
        }
        __syncthreads();
    }

#pragma unroll
    for (int i = 0; i < 2; i++) {
        int gn = rt + tr * 2 + i;
#pragma unroll
        for (int j = 0; j < 4; j++) {
            int gd = dt + tc * 4 + j;
            out[((long)b * Nn + gn) * Dd + gd] = acc[i][j] + Bf[(long)gn * Dd + gd];
        }
    }
}

// -------- gated moment reduction: out += sum_i A[i,j]*fm*sigmoid(fm*s) ----
// block per (b,j), 512 threads: 4 i-chunks x 128 d-groups (float4). smem reduce.
__global__ void moment_kernel(const float* __restrict__ S,
                              const float* __restrict__ f_m,
                              const float* __restrict__ f_s,
                              float* __restrict__ out)
{
    int j = blockIdx.x, b = blockIdx.y;
    int t = threadIdx.x;                  // 0..511
    int dt = t & 127;                     // d-group: d = 4*dt
    int ig = t >> 7;                      // 0..3

    __shared__ float Acol[Nn];
    __shared__ float4 red[4][128];        // 8KB
    if (t < Nn) Acol[t] = S[(long)(b * Nn + t) * Nn + j];
    __syncthreads();

    float4 s = *(const float4*)(f_s + (long)b * Dd + 4 * dt);
    float hx = 0.5f * s.x, hy = 0.5f * s.y, hz = 0.5f * s.z, hw = 0.5f * s.w;
    const float4* fm = (const float4*)(f_m + ((long)(b * Nn) * Nn + j) * Dd) + dt;
    const long istep = (long)Nn * Dd / 4;

    float ax = 0.f, ay = 0.f, az = 0.f, aw = 0.f;
#pragma unroll 8
    for (int ii = 0; ii < Nn / 4; ii++) {
        int i = ig * (Nn / 4) + ii;
        float4 x = __ldcs(&fm[(long)i * istep]);
        float a = Acol[i];
        ax = fmaf(a * x.x, fmaf(tanh_approx(x.x * hx), 0.5f, 0.5f), ax);
        ay = fmaf(a * x.y, fmaf(tanh_approx(x.y * hy), 0.5f, 0.5f), ay);
        az = fmaf(a * x.z, fmaf(tanh_approx(x.z * hz), 0.5f, 0.5f), az);
        aw = fmaf(a * x.w, fmaf(tanh_approx(x.w * hw), 0.5f, 0.5f), aw);
    }
    red[ig][dt] = make_float4(ax, ay, az, aw);
    __syncthreads();

    if (t < 128) {
        float4 r0 = red[0][t], r1 = red[1][t], r2 = red[2][t], r3 = red[3][t];
        float4* op = (float4*)(out + (long)(b * Nn + j) * Dd) + t;
        float4 r = *op;
        r.x += r0.x + r1.x + r2.x + r3.x;
        r.y += r0.y + r1.y + r2.y + r3.y;
        r.z += r0.z + r1.z + r2.z + r3.z;
        r.w += r0.w + r1.w + r2.w + r3.w;
        *op = r;
    }
}

// ---------------- launch ----------------
extern "C" void kernel_launch(void* const* d_in, const int* in_sizes, int n_in,
                              void* d_out, int out_size)
{
    const float* f_b = (const float*)d_in[0];
    const float* f_w = (const float*)d_in[1];
    const float* f_s = (const float*)d_in[2];
    const float* f_m = (const float*)d_in[3];
    const float* Wq  = (const float*)d_in[4];
    const float* bq  = (const float*)d_in[5];
    const float* Wk  = (const float*)d_in[6];
    const float* bk  = (const float*)d_in[7];
    float* out = (float*)d_out;

    float* kk  = nullptr; cudaGetSymbolAddress((void**)&kk,  g_k);
    float* u   = nullptr; cudaGetSymbolAddress((void**)&u,   g_u);
    float* fbq = nullptr; cudaGetSymbolAddress((void**)&fbq, g_fbq);
    float* S   = nullptr; cudaGetSymbolAddress((void**)&S,   g_S);
    float* Sp  = nullptr; cudaGetSymbolAddress((void**)&Sp,  g_Sp);

    cudaFuncSetAttribute(cross_attn8, cudaFuncAttributeMaxDynamicSharedMemorySize, CROSS_SMEM);

    // 1) k = f_w @ Wk^T + bk   [80,512]
    {
        dim3 grid(Dd / 32, (Bb * Ll) / 16);
        gemm_nt32<<<grid, 128>>>(f_w, Wk, bk, kk);
    }
    // 2) u = k @ Wq            [80,512]
    {
        dim3 grid(Dd / 32, (Bb * Ll) / 16);
        gemm_nn32<<<grid, 128>>>(kk, Wq, u);
    }
    // 3) cross attention + gate -> f_bq
    {
        dim3 grid(Nn / 8, Bb);
        cross_attn8<<<grid, 512, CROSS_SMEM>>>(u, kk, bq, f_w, f_b, f_s, fbq);
    }
    // 4) S partials = split-K f_bq @ f_bq^T
    {
        dim3 grid(Nn / 32, Nn / 32, Bb * KS);
        s_gemm_kernel<<<grid, 256>>>(fbq, Sp);
    }
    // 5) fused reduce + softmax + fbb: writes S and out = A_b@f_b + f_b
    {
        dim3 grid(Dd / 64, Nn / 32, Bb);
        softmax_fbb_kernel<<<grid, 256>>>(Sp, f_b, S, out);
    }
    // 6) moment: out += gated moment reduction
    {
        dim3 grid(Nn, Bb);
        moment_kernel<<<grid, 512>>>(S, f_m, f_s, out);
    }
    (void)in_sizes; (void)n_in; (void)out_size;
}